// round 4
// baseline (speedup 1.0000x reference)
#include <cuda_runtime.h>

// v' = A*v + B*i  (A = 0.625, B = 0.075), warp-cooperative affine scan.
// R4: ONE WARP PER ROW, sequential over 32 tiles of 256 with exact carry
// (A^256 underflows fp32 -> carry = b31). No warm-up reads. grid=1024
// CTAs x 128 thr -> 6.92 CTAs/SM << reg-limit 12 -> guaranteed single wave.

#define NN     4096
#define TT     8192
#define TILES  (TT / 256)          // 32 tiles per row

#define A1f 0.625f
#define A2f 0.390625f
#define A3f 0.244140625f
#define A4f 0.152587890625f
#define A5f 0.095367431640625f
#define A6f 0.059604644775390625f
#define A7f 0.037252902984619140625f
#define A8f 0.02328306436538696289f
#define A16f 5.4210108624275222e-4f
#define A32f 2.9387358770557188e-7f
#define A64f 8.6361685550944446e-14f
#define A128f 7.4583407312002067e-27f
#define Bf  0.075f

// Scan one 256-element tile already loaded into (xa, xb). Stores results,
// returns carry-out (= b31 exactly; A^256 underflows to 0).
__device__ __forceinline__ float tile_scan256(float4 xa, float4 xb,
                                              float4* __restrict__ q,
                                              float carry, float apl, int lane)
{
    float c0 = Bf * xa.x;
    float c1 = fmaf(A1f, c0, Bf * xa.y);
    float c2 = fmaf(A1f, c1, Bf * xa.z);
    float c3 = fmaf(A1f, c2, Bf * xa.w);
    float c4 = fmaf(A1f, c3, Bf * xb.x);
    float c5 = fmaf(A1f, c4, Bf * xb.y);
    float c6 = fmaf(A1f, c5, Bf * xb.z);
    float c7 = fmaf(A1f, c6, Bf * xb.w);

    float b = c7, t;
    t = __shfl_up_sync(0xffffffffu, b, 1);  if (lane >= 1)  b = fmaf(A8f,   t, b);
    t = __shfl_up_sync(0xffffffffu, b, 2);  if (lane >= 2)  b = fmaf(A16f,  t, b);
    t = __shfl_up_sync(0xffffffffu, b, 4);  if (lane >= 4)  b = fmaf(A32f,  t, b);
    t = __shfl_up_sync(0xffffffffu, b, 8);  if (lane >= 8)  b = fmaf(A64f,  t, b);
    t = __shfl_up_sync(0xffffffffu, b, 16); if (lane >= 16) b = fmaf(A128f, t, b);

    float bp = __shfl_up_sync(0xffffffffu, b, 1);
    if (lane == 0) bp = 0.0f;
    float P = fmaf(apl, carry, bp);

    float4 ya, yb;
    ya.x = fmaf(A1f, P, c0);
    ya.y = fmaf(A2f, P, c1);
    ya.z = fmaf(A3f, P, c2);
    ya.w = fmaf(A4f, P, c3);
    yb.x = fmaf(A5f, P, c4);
    yb.y = fmaf(A6f, P, c5);
    yb.z = fmaf(A7f, P, c6);
    yb.w = fmaf(A8f, P, c7);
    __stcs(q + 2 * lane, ya);
    __stcs(q + 2 * lane + 1, yb);

    return __shfl_sync(0xffffffffu, b, 31);
}

__global__ __launch_bounds__(128)
void nonspiking_rowscan_kernel(const float* __restrict__ in, float* __restrict__ out)
{
    int warp = (blockIdx.x * blockDim.x + threadIdx.x) >> 5;  // row 0..4095
    int lane = threadIdx.x & 31;

    const float4* p = reinterpret_cast<const float4*>(in  + (size_t)warp * TT);
    float4*       q = reinterpret_cast<float4*>(out + (size_t)warp * TT);

    // apl = A^(8*lane) by square-and-multiply (underflow for high lanes is fine)
    float apl = 1.0f, aa = A8f;
    int e = lane;
    #pragma unroll
    for (int k = 0; k < 5; ++k) { if (e & 1) apl *= aa; aa *= aa; e >>= 1; }

    // Prefetch tile 0.
    float4 xa = __ldcs(p + 2 * lane);
    float4 xb = __ldcs(p + 2 * lane + 1);

    float carry = 0.0f;
    #pragma unroll 4
    for (int t = 0; t < TILES; ++t) {
        float4 na, nb;
        if (t + 1 < TILES) {
            na = __ldcs(p + (t + 1) * 64 + 2 * lane);
            nb = __ldcs(p + (t + 1) * 64 + 2 * lane + 1);
        }
        carry = tile_scan256(xa, xb, q + t * 64, carry, apl, lane);
        xa = na; xb = nb;
    }
}

extern "C" void kernel_launch(void* const* d_in, const int* in_sizes, int n_in,
                              void* d_out, int out_size)
{
    const float* in = (const float*)d_in[0];
    float* out = (float*)d_out;
    (void)in_sizes; (void)n_in; (void)out_size;

    int block = 128;                 // 4 warps
    int grid = NN * 32 / block;      // 1024 CTAs -> single wave
    nonspiking_rowscan_kernel<<<grid, block>>>(in, out);
}

// round 5
// speedup vs baseline: 1.0767x; 1.0767x over previous
#include <cuda_runtime.h>

// v' = A*v + B*i  (A = 0.625, B = 0.075), block-cooperative affine scan.
// R5: one CTA (4 warps) per row, 4KB-contiguous tiles (1024 floats). A^256
// underflows fp32 exactly, so warp w's prefix within a tile is just b31 of
// warp w-1 (parallel; exchanged via one smem word + 1 syncthreads), and the
// tile carry is warp 3's b31. Goal: 4x larger DRAM bursts per stream.

#define NN     4096
#define TT     8192
#define CTILE  1024                // floats per CTA tile (4 warps x 256)
#define TILES  (TT / CTILE)        // 8 tiles per row

#define A1f 0.625f
#define A2f 0.390625f
#define A3f 0.244140625f
#define A4f 0.152587890625f
#define A5f 0.095367431640625f
#define A6f 0.059604644775390625f
#define A7f 0.037252902984619140625f
#define A8f 0.02328306436538696289f
#define A16f 5.4210108624275222e-4f
#define A32f 2.9387358770557188e-7f
#define A64f 8.6361685550944446e-14f
#define A128f 7.4583407312002067e-27f
#define Bf  0.075f

__global__ __launch_bounds__(128)
void nonspiking_blockscan_kernel(const float* __restrict__ in, float* __restrict__ out)
{
    __shared__ float s_b31[2][4];      // [tile parity][warp] summaries

    int row  = blockIdx.x;
    int w    = threadIdx.x >> 5;
    int lane = threadIdx.x & 31;

    // warp w owns floats [t*1024 + w*256 + lane*8, +8) => float4 idx w*64 + 2*lane
    const float4* p = reinterpret_cast<const float4*>(in  + (size_t)row * TT) + w * 64;
    float4*       q = reinterpret_cast<float4*>(out + (size_t)row * TT) + w * 64;

    // apl = A^(8*lane) by square-and-multiply
    float apl = 1.0f, aa = A8f;
    int e = lane;
    #pragma unroll
    for (int k = 0; k < 5; ++k) { if (e & 1) apl *= aa; aa *= aa; e >>= 1; }

    // Prefetch tile 0 (CTA reads 4KB contiguous: all 4 warps adjacent).
    float4 xa = __ldcs(p + 2 * lane);
    float4 xb = __ldcs(p + 2 * lane + 1);

    float carry = 0.0f;
    #pragma unroll
    for (int t = 0; t < TILES; ++t) {
        // Prefetch next tile before any barrier (keeps LDGs in flight).
        float4 na, nb;
        if (t + 1 < TILES) {
            na = __ldcs(p + (t + 1) * 256 + 2 * lane);
            nb = __ldcs(p + (t + 1) * 256 + 2 * lane + 1);
        }

        // Local cumulative terms for this lane's 8 steps.
        float c0 = Bf * xa.x;
        float c1 = fmaf(A1f, c0, Bf * xa.y);
        float c2 = fmaf(A1f, c1, Bf * xa.z);
        float c3 = fmaf(A1f, c2, Bf * xa.w);
        float c4 = fmaf(A1f, c3, Bf * xb.x);
        float c5 = fmaf(A1f, c4, Bf * xb.y);
        float c6 = fmaf(A1f, c5, Bf * xb.z);
        float c7 = fmaf(A1f, c6, Bf * xb.w);

        // Kogge-Stone over lane summaries (step-s multiplier = A^(8s)).
        float b = c7, s;
        s = __shfl_up_sync(0xffffffffu, b, 1);  if (lane >= 1)  b = fmaf(A8f,   s, b);
        s = __shfl_up_sync(0xffffffffu, b, 2);  if (lane >= 2)  b = fmaf(A16f,  s, b);
        s = __shfl_up_sync(0xffffffffu, b, 4);  if (lane >= 4)  b = fmaf(A32f,  s, b);
        s = __shfl_up_sync(0xffffffffu, b, 8);  if (lane >= 8)  b = fmaf(A64f,  s, b);
        s = __shfl_up_sync(0xffffffffu, b, 16); if (lane >= 16) b = fmaf(A128f, s, b);

        // Publish warp summary (lane 31 holds b31 = this warp's segment scan).
        if (lane == 31) s_b31[t & 1][w] = b;
        __syncthreads();

        // Warp carry-in: tile carry for warp 0, b31 of warp w-1 otherwise
        // (terms beyond one warp back carry A^256 = 0 exactly in fp32).
        float cw = (w == 0) ? carry : s_b31[t & 1][w - 1];

        float bp = __shfl_up_sync(0xffffffffu, b, 1);
        if (lane == 0) bp = 0.0f;
        float P = fmaf(apl, cw, bp);

        float4 ya, yb;
        ya.x = fmaf(A1f, P, c0);
        ya.y = fmaf(A2f, P, c1);
        ya.z = fmaf(A3f, P, c2);
        ya.w = fmaf(A4f, P, c3);
        yb.x = fmaf(A5f, P, c4);
        yb.y = fmaf(A6f, P, c5);
        yb.z = fmaf(A7f, P, c6);
        yb.w = fmaf(A8f, P, c7);
        __stcs(q + t * 256 + 2 * lane, ya);       // CTA writes 4KB contiguous
        __stcs(q + t * 256 + 2 * lane + 1, yb);

        carry = s_b31[t & 1][3];                  // tile carry = warp 3's b31
        xa = na; xb = nb;
    }
}

extern "C" void kernel_launch(void* const* d_in, const int* in_sizes, int n_in,
                              void* d_out, int out_size)
{
    const float* in = (const float*)d_in[0];
    float* out = (float*)d_out;
    (void)in_sizes; (void)n_in; (void)out_size;

    nonspiking_blockscan_kernel<<<NN, 128>>>(in, out);   // one CTA per row
}